// round 5
// baseline (speedup 1.0000x reference)
#include <cuda_runtime.h>
#include <cstdint>

// x (256,18,18,512) f32, W (18,512,512) f32, b (18,512) f32, idx (18) i32
#define KB_   256
#define O_    18
#define J_    18
#define DIM   512
#define M_TOTAL (KB_ * J_)        // 4608
#define BM    128
#define BN    256
#define BK    16
#define ST    20                  // smem row stride (u32): BK + 4 pad (bank-clean)
#define NKT   (DIM / BK)          // 32
#define STAGES 4
#define SCALE_F 0.044194173824159216f

#define SA_U32 (BM * ST)                    // 2560
#define SB_U32 (BN * ST)                    // 5120
#define STG_U32 (SA_U32 + SB_U32)           // 7680 u32 = 30720 B
#define SMEM_BYTES (STAGES * STG_U32 * 4)   // 122880

__device__ int g_sel[J_];
__device__ float g_Wt[O_ * DIM * DIM];      // W pre-converted to tf32 bit patterns

__global__ void build_sel_kernel(const int* __restrict__ idx, int n) {
    int t = threadIdx.x;
    if (t < J_) g_sel[t] = 0;
    __syncthreads();
    if (t < n) {
        int v = idx[t];
        if (v >= 0 && v < J_) g_sel[v] = 1;
    }
}

__device__ __forceinline__ uint32_t f2tf32(float f) {
    uint32_t u;
    asm("cvt.rna.tf32.f32 %0, %1;" : "=r"(u) : "f"(f));
    return u;
}

__global__ void convert_w_kernel(const float* __restrict__ W) {
    const int total4 = O_ * DIM * DIM / 4;
    for (int i = blockIdx.x * blockDim.x + threadIdx.x; i < total4;
         i += gridDim.x * blockDim.x) {
        float4 v = reinterpret_cast<const float4*>(W)[i];
        uint4 u = make_uint4(f2tf32(v.x), f2tf32(v.y), f2tf32(v.z), f2tf32(v.w));
        reinterpret_cast<uint4*>(g_Wt)[i] = u;
    }
}

__device__ __forceinline__ uint32_t smem_u32(const void* p) {
    uint32_t a;
    asm("{ .reg .u64 t; cvta.to.shared.u64 t, %1; cvt.u32.u64 %0, t; }" : "=r"(a) : "l"(p));
    return a;
}

__device__ __forceinline__ void cp16(uint32_t dst, const void* src) {
    asm volatile("cp.async.cg.shared.global [%0], [%1], 16;" :: "r"(dst), "l"(src));
}

__global__ __launch_bounds__(256, 1)
void dirnet_gemm_kernel(const float* __restrict__ x, const float* __restrict__ bias,
                        float* __restrict__ out) {
    extern __shared__ uint32_t sm[];
    const uint32_t smb = smem_u32(sm);

    const int o   = blockIdx.z;
    const int mt  = blockIdx.y;
    const int nt  = blockIdx.x;
    const int tid = threadIdx.x;
    const int lane = tid & 31;
    const int wid  = tid >> 5;
    const int g  = lane >> 2;   // 0..7
    const int t4 = lane & 3;    // 0..3
    const int wm = wid >> 2;    // 0..1 -> 64 rows
    const int wn = wid & 3;     // 0..3 -> 64 cols

    // ---- producer addressing ----
    // A: 512 float4/ktile -> 2 per thread (LDG->cvt->STS path)
    int aOff[2], tAOff[2];
    #pragma unroll
    for (int it = 0; it < 2; it++) {
        int f   = it * 256 + tid;
        int row = f >> 2;
        int c4  = f & 3;
        int m   = mt * BM + row;
        int kb  = m / J_;
        int j   = m - kb * J_;
        aOff[it]  = ((kb * O_ + o) * J_ + j) * DIM + c4 * 4;
        tAOff[it] = row * ST + c4 * 4;
    }
    // B: 1024 float4/ktile -> 4 per thread (cp.async from g_Wt)
    int bOff[4];
    uint32_t tBOff[4];
    #pragma unroll
    for (int it = 0; it < 4; it++) {
        int f   = it * 256 + tid;
        int row = f >> 2;
        int c4  = f & 3;
        bOff[it]  = o * (DIM * DIM) + (nt * BN + row) * DIM + c4 * 4;
        tBOff[it] = (SA_U32 + row * ST + c4 * 4) * 4;   // byte offset within stage
    }

    // ---- prologue: fill stages 0..2, prefetch A tile 3 into registers ----
    float4 ra[2];
    #pragma unroll
    for (int s = 0; s < 3; s++) {
        uint32_t base = smb + s * STG_U32 * 4;
        #pragma unroll
        for (int it = 0; it < 4; it++)
            cp16(base + tBOff[it], g_Wt + bOff[it] + s * BK);
        #pragma unroll
        for (int it = 0; it < 2; it++) {
            float4 v = *reinterpret_cast<const float4*>(x + aOff[it] + s * BK);
            uint4 u = make_uint4(f2tf32(v.x), f2tf32(v.y), f2tf32(v.z), f2tf32(v.w));
            *reinterpret_cast<uint4*>(&sm[s * STG_U32 + tAOff[it]]) = u;
        }
        asm volatile("cp.async.commit_group;" ::: "memory");
    }
    #pragma unroll
    for (int it = 0; it < 2; it++)
        ra[it] = *reinterpret_cast<const float4*>(x + aOff[it] + 3 * BK);

    float acc[4][8][4];
    #pragma unroll
    for (int a = 0; a < 4; a++)
        #pragma unroll
        for (int b = 0; b < 8; b++)
            #pragma unroll
            for (int c = 0; c < 4; c++) acc[a][b][c] = 0.f;

    const int mBase = wm * 64;
    const int nBase = wn * 64;

    for (int kt = 0; kt < NKT; kt++) {
        const int cur = kt % STAGES;
        asm volatile("cp.async.wait_group 2;" ::: "memory");
        __syncthreads();

        // refill stage kt+3 (consumed at kt-1)
        if (kt + 3 < NKT) {
            const int nxt = (kt + 3) % STAGES;
            uint32_t base = smb + nxt * STG_U32 * 4;
            #pragma unroll
            for (int it = 0; it < 4; it++)
                cp16(base + tBOff[it], g_Wt + bOff[it] + (kt + 3) * BK);
            #pragma unroll
            for (int it = 0; it < 2; it++) {
                uint4 u = make_uint4(f2tf32(ra[it].x), f2tf32(ra[it].y),
                                     f2tf32(ra[it].z), f2tf32(ra[it].w));
                *reinterpret_cast<uint4*>(&sm[nxt * STG_U32 + tAOff[it]]) = u;
            }
        }
        asm volatile("cp.async.commit_group;" ::: "memory");
        if (kt + 4 < NKT) {
            #pragma unroll
            for (int it = 0; it < 2; it++)
                ra[it] = *reinterpret_cast<const float4*>(x + aOff[it] + (kt + 4) * BK);
        }

        const uint32_t* cA = sm + cur * STG_U32;
        const uint32_t* cB = cA + SA_U32;

        #pragma unroll
        for (int ks = 0; ks < 2; ks++) {
            const int k0 = ks * 8;
            uint32_t af[4][4], bf[8][2];
            #pragma unroll
            for (int mf = 0; mf < 4; mf++) {
                int r = (mBase + mf * 16 + g) * ST + k0 + t4;
                af[mf][0] = cA[r];
                af[mf][1] = cA[r + 8 * ST];
                af[mf][2] = cA[r + 4];
                af[mf][3] = cA[r + 8 * ST + 4];
            }
            #pragma unroll
            for (int nf = 0; nf < 8; nf++) {
                int r = (nBase + nf * 8 + g) * ST + k0 + t4;
                bf[nf][0] = cB[r];
                bf[nf][1] = cB[r + 4];
            }
            #pragma unroll
            for (int mf = 0; mf < 4; mf++)
                #pragma unroll
                for (int nf = 0; nf < 8; nf++) {
                    asm volatile(
                        "mma.sync.aligned.m16n8k8.row.col.f32.tf32.tf32.f32 "
                        "{%0,%1,%2,%3}, {%4,%5,%6,%7}, {%8,%9}, {%0,%1,%2,%3};\n"
                        : "+f"(acc[mf][nf][0]), "+f"(acc[mf][nf][1]),
                          "+f"(acc[mf][nf][2]), "+f"(acc[mf][nf][3])
                        : "r"(af[mf][0]), "r"(af[mf][1]), "r"(af[mf][2]), "r"(af[mf][3]),
                          "r"(bf[nf][0]), "r"(bf[nf][1]));
                }
        }
    }

    // ---- epilogue ----
    const float* bRow = bias + o * DIM + nt * BN;
    #pragma unroll
    for (int mf = 0; mf < 4; mf++) {
        #pragma unroll
        for (int half = 0; half < 2; half++) {
            int mloc = mBase + mf * 16 + g + half * 8;
            int m  = mt * BM + mloc;
            int kb = m / J_;
            int j  = m - kb * J_;
            int rowOff = ((kb * O_ + o) * J_ + j) * DIM + nt * BN;
            int selv = g_sel[j];
            #pragma unroll
            for (int nf = 0; nf < 8; nf++) {
                int n = nBase + nf * 8 + t4 * 2;
                float v0, v1;
                if (selv) {
                    v0 = acc[mf][nf][half * 2 + 0] * SCALE_F + bRow[n];
                    v1 = acc[mf][nf][half * 2 + 1] * SCALE_F + bRow[n + 1];
                } else {
                    v0 = x[rowOff + n];
                    v1 = x[rowOff + n + 1];
                }
                *reinterpret_cast<float2*>(out + rowOff + n) = make_float2(v0, v1);
            }
        }
    }
}

extern "C" void kernel_launch(void* const* d_in, const int* in_sizes, int n_in,
                              void* d_out, int out_size) {
    const float* x   = (const float*)d_in[0];
    const float* W   = (const float*)d_in[1];
    const float* b   = (const float*)d_in[2];
    const int*   idx = (const int*)d_in[3];
    float* out = (float*)d_out;

    build_sel_kernel<<<1, 32>>>(idx, in_sizes[3]);
    convert_w_kernel<<<1024, 256>>>(W);

    cudaFuncSetAttribute(dirnet_gemm_kernel,
                         cudaFuncAttributeMaxDynamicSharedMemorySize, SMEM_BYTES);

    dim3 grid(DIM / BN, M_TOTAL / BM, O_);
    dirnet_gemm_kernel<<<grid, 256, SMEM_BYTES>>>(x, b, out);
}

// round 6
// speedup vs baseline: 1.1172x; 1.1172x over previous
#include <cuda_runtime.h>
#include <cstdint>

// x (256,18,18,512) f32, W (18,512,512) f32, b (18,512) f32, idx (18) i32
#define KB_   256
#define O_    18
#define J_    18
#define DIM   512
#define M_TOTAL (KB_ * J_)        // 4608
#define BM    128
#define BN    128
#define BK    16
#define ST    20                  // smem row stride (u32): BK + 4 pad (conflict-free for LDSM)
#define NKT   (DIM / BK)          // 32
#define STAGES 3
#define SCALE_F 0.044194173824159216f

#define SA_U32 (BM * ST)                    // 2560
#define SB_U32 (BN * ST)                    // 2560
#define STG_U32 (SA_U32 + SB_U32)           // 5120
#define SMEM_BYTES (STAGES * STG_U32 * 4)   // 61440

__device__ int g_sel[J_];
__device__ float g_Wt[O_ * DIM * DIM];      // W pre-converted to tf32 bit patterns

__global__ void build_sel_kernel(const int* __restrict__ idx, int n) {
    int t = threadIdx.x;
    if (t < J_) g_sel[t] = 0;
    __syncthreads();
    if (t < n) {
        int v = idx[t];
        if (v >= 0 && v < J_) g_sel[v] = 1;
    }
}

__device__ __forceinline__ uint32_t f2tf32(float f) {
    uint32_t u;
    asm("cvt.rna.tf32.f32 %0, %1;" : "=r"(u) : "f"(f));
    return u;
}

__global__ void convert_w_kernel(const float* __restrict__ W) {
    const int total4 = O_ * DIM * DIM / 4;
    for (int i = blockIdx.x * blockDim.x + threadIdx.x; i < total4;
         i += gridDim.x * blockDim.x) {
        float4 v = reinterpret_cast<const float4*>(W)[i];
        uint4 u = make_uint4(f2tf32(v.x), f2tf32(v.y), f2tf32(v.z), f2tf32(v.w));
        reinterpret_cast<uint4*>(g_Wt)[i] = u;
    }
}

__device__ __forceinline__ uint32_t smem_u32(const void* p) {
    uint32_t a;
    asm("{ .reg .u64 t; cvta.to.shared.u64 t, %1; cvt.u32.u64 %0, t; }" : "=r"(a) : "l"(p));
    return a;
}

__device__ __forceinline__ void cp16(uint32_t dst, const void* src) {
    asm volatile("cp.async.cg.shared.global [%0], [%1], 16;" :: "r"(dst), "l"(src));
}

__device__ __forceinline__ void ldsm_x4(uint32_t* r, uint32_t addr) {
    asm volatile("ldmatrix.sync.aligned.m8n8.x4.shared.b16 {%0,%1,%2,%3}, [%4];"
                 : "=r"(r[0]), "=r"(r[1]), "=r"(r[2]), "=r"(r[3]) : "r"(addr));
}

__device__ __forceinline__ void ldsm_x2(uint32_t* r, uint32_t addr) {
    asm volatile("ldmatrix.sync.aligned.m8n8.x2.shared.b16 {%0,%1}, [%2];"
                 : "=r"(r[0]), "=r"(r[1]) : "r"(addr));
}

__global__ __launch_bounds__(256, 2)
void dirnet_gemm_kernel(const float* __restrict__ x, const float* __restrict__ bias,
                        float* __restrict__ out) {
    extern __shared__ uint32_t sm[];
    const uint32_t smb = smem_u32(sm);

    const int o   = blockIdx.z;
    const int mt  = blockIdx.y;
    const int nt  = blockIdx.x;
    const int tid = threadIdx.x;
    const int lane = tid & 31;
    const int wid  = tid >> 5;
    const int g  = lane >> 2;   // 0..7
    const int t4 = lane & 3;    // 0..3
    const int wm = wid >> 2;    // 0..1 -> 64 rows
    const int wn = wid & 3;     // 0..3 -> 32 cols
    const int mBase = wm * 64;
    const int nBase = wn * 32;

    // ---- producer addressing: per thread 2 float4 of A (LDG->cvt->STS), 2 of B (cp.async) ----
    int aOff[2], bOff[2];
    uint32_t tAOff[2], tBOff[2];
    #pragma unroll
    for (int it = 0; it < 2; it++) {
        int f   = it * 256 + tid;
        int row = f >> 2;        // 0..127
        int c4  = f & 3;
        int m   = mt * BM + row;
        int kb  = m / J_;
        int j   = m - kb * J_;
        aOff[it]  = ((kb * O_ + o) * J_ + j) * DIM + c4 * 4;
        bOff[it]  = o * (DIM * DIM) + (nt * BN + row) * DIM + c4 * 4;
        tAOff[it] = row * ST + c4 * 4;                 // u32 offset in stage A block
        tBOff[it] = (SA_U32 + row * ST + c4 * 4) * 4;  // byte offset in stage
    }

    // ---- ldmatrix per-thread source addresses (byte offsets within a stage) ----
    const int r8  = lane & 7;
    const int seg = lane >> 3;          // 0..3
    uint32_t ofA[4], ofB[4];
    #pragma unroll
    for (int mf = 0; mf < 4; mf++)
        ofA[mf] = (uint32_t)(((mBase + mf * 16 + (seg & 1) * 8 + r8) * ST + (seg >> 1) * 4) * 4);
    #pragma unroll
    for (int nf = 0; nf < 4; nf++)
        ofB[nf] = (uint32_t)((SA_U32 + (nBase + nf * 8 + r8) * ST + (seg & 1) * 4) * 4);

    // ---- prologue: stages 0,1 in flight; A(2) prefetched to regs ----
    float4 ra[2];
    #pragma unroll
    for (int s = 0; s < 2; s++) {
        uint32_t base = smb + s * STG_U32 * 4;
        #pragma unroll
        for (int it = 0; it < 2; it++) {
            cp16(base + tBOff[it], g_Wt + bOff[it] + s * BK);
            float4 v = *reinterpret_cast<const float4*>(x + aOff[it] + s * BK);
            uint4 u = make_uint4(f2tf32(v.x), f2tf32(v.y), f2tf32(v.z), f2tf32(v.w));
            *reinterpret_cast<uint4*>(&sm[s * STG_U32 + tAOff[it]]) = u;
        }
        asm volatile("cp.async.commit_group;" ::: "memory");
    }
    #pragma unroll
    for (int it = 0; it < 2; it++)
        ra[it] = *reinterpret_cast<const float4*>(x + aOff[it] + 2 * BK);

    float acc[4][4][4];
    #pragma unroll
    for (int a = 0; a < 4; a++)
        #pragma unroll
        for (int b = 0; b < 4; b++)
            #pragma unroll
            for (int c = 0; c < 4; c++) acc[a][b][c] = 0.f;

    for (int kt = 0; kt < NKT; kt++) {
        const int cur = kt % STAGES;
        asm volatile("cp.async.wait_group 1;" ::: "memory");
        __syncthreads();

        // refill stage kt+2
        if (kt + 2 < NKT) {
            const int nxt = (kt + 2) % STAGES;
            uint32_t base = smb + nxt * STG_U32 * 4;
            #pragma unroll
            for (int it = 0; it < 2; it++) {
                cp16(base + tBOff[it], g_Wt + bOff[it] + (kt + 2) * BK);
                uint4 u = make_uint4(f2tf32(ra[it].x), f2tf32(ra[it].y),
                                     f2tf32(ra[it].z), f2tf32(ra[it].w));
                *reinterpret_cast<uint4*>(&sm[nxt * STG_U32 + tAOff[it]]) = u;
            }
        }
        asm volatile("cp.async.commit_group;" ::: "memory");
        if (kt + 3 < NKT) {
            #pragma unroll
            for (int it = 0; it < 2; it++)
                ra[it] = *reinterpret_cast<const float4*>(x + aOff[it] + (kt + 3) * BK);
        }

        const uint32_t sbase = smb + cur * STG_U32 * 4;

        #pragma unroll
        for (int ks = 0; ks < 2; ks++) {
            const uint32_t kadd = (uint32_t)(ks * 32);   // 8 u32 = 32 B
            uint32_t af[4][4], bf[4][2];
            #pragma unroll
            for (int mf = 0; mf < 4; mf++)
                ldsm_x4(af[mf], sbase + ofA[mf] + kadd);
            #pragma unroll
            for (int nf = 0; nf < 4; nf++)
                ldsm_x2(bf[nf], sbase + ofB[nf] + kadd);

            #pragma unroll
            for (int mf = 0; mf < 4; mf++)
                #pragma unroll
                for (int nf = 0; nf < 4; nf++) {
                    asm volatile(
                        "mma.sync.aligned.m16n8k8.row.col.f32.tf32.tf32.f32 "
                        "{%0,%1,%2,%3}, {%4,%5,%6,%7}, {%8,%9}, {%0,%1,%2,%3};\n"
                        : "+f"(acc[mf][nf][0]), "+f"(acc[mf][nf][1]),
                          "+f"(acc[mf][nf][2]), "+f"(acc[mf][nf][3])
                        : "r"(af[mf][0]), "r"(af[mf][1]), "r"(af[mf][2]), "r"(af[mf][3]),
                          "r"(bf[nf][0]), "r"(bf[nf][1]));
                }
        }
    }

    // ---- epilogue ----
    const float* bRow = bias + o * DIM;
    #pragma unroll
    for (int mf = 0; mf < 4; mf++) {
        #pragma unroll
        for (int half = 0; half < 2; half++) {
            int mloc = mBase + mf * 16 + g + half * 8;
            int m  = mt * BM + mloc;
            int kb = m / J_;
            int j  = m - kb * J_;
            int rowOff = ((kb * O_ + o) * J_ + j) * DIM;
            int selv = g_sel[j];
            #pragma unroll
            for (int nf = 0; nf < 4; nf++) {
                int n = nt * BN + nBase + nf * 8 + t4 * 2;
                float v0, v1;
                if (selv) {
                    v0 = acc[mf][nf][half * 2 + 0] * SCALE_F + bRow[n];
                    v1 = acc[mf][nf][half * 2 + 1] * SCALE_F + bRow[n + 1];
                } else {
                    v0 = x[rowOff + n];
                    v1 = x[rowOff + n + 1];
                }
                *reinterpret_cast<float2*>(out + rowOff + n) = make_float2(v0, v1);
            }
        }
    }
}

extern "C" void kernel_launch(void* const* d_in, const int* in_sizes, int n_in,
                              void* d_out, int out_size) {
    const float* x   = (const float*)d_in[0];
    const float* W   = (const float*)d_in[1];
    const float* b   = (const float*)d_in[2];
    const int*   idx = (const int*)d_in[3];
    float* out = (float*)d_out;

    build_sel_kernel<<<1, 32>>>(idx, in_sizes[3]);
    convert_w_kernel<<<1024, 256>>>(W);

    cudaFuncSetAttribute(dirnet_gemm_kernel,
                         cudaFuncAttributeMaxDynamicSharedMemorySize, SMEM_BYTES);

    dim3 grid(DIM / BN, M_TOTAL / BM, O_);
    dirnet_gemm_kernel<<<grid, 256, SMEM_BYTES>>>(x, b, out);
}

// round 7
// speedup vs baseline: 1.1998x; 1.0740x over previous
#include <cuda_runtime.h>
#include <cstdint>

// x (256,18,18,512) f32, W (18,512,512) f32, b (18,512) f32, idx (18) i32
#define KB_   256
#define O_    18
#define J_    18
#define DIM   512
#define M_TOTAL (KB_ * J_)        // 4608
#define BM    128
#define BN    128
#define BK    32
#define ST    36                  // smem row stride (u32): BK + 4 pad (conflict-free LDSM/STS)
#define NKT   (DIM / BK)          // 16
#define STAGES 3
#define SCALE_F 0.044194173824159216f

#define SA_U32 (BM * ST)                    // 4608
#define SB_U32 (BN * ST)                    // 4608
#define STG_U32 (SA_U32 + SB_U32)           // 9216 u32 = 36864 B
#define SMEM_BYTES (STAGES * STG_U32 * 4)   // 110592

__device__ int g_sel[J_];
__device__ float g_Wt[O_ * DIM * DIM];      // W pre-converted to tf32 bit patterns

__global__ void build_sel_kernel(const int* __restrict__ idx, int n) {
    int t = threadIdx.x;
    if (t < J_) g_sel[t] = 0;
    __syncthreads();
    if (t < n) {
        int v = idx[t];
        if (v >= 0 && v < J_) g_sel[v] = 1;
    }
}

__device__ __forceinline__ uint32_t f2tf32(float f) {
    uint32_t u;
    asm("cvt.rna.tf32.f32 %0, %1;" : "=r"(u) : "f"(f));
    return u;
}

__global__ void convert_w_kernel(const float* __restrict__ W) {
    const int total4 = O_ * DIM * DIM / 4;
    for (int i = blockIdx.x * blockDim.x + threadIdx.x; i < total4;
         i += gridDim.x * blockDim.x) {
        float4 v = reinterpret_cast<const float4*>(W)[i];
        uint4 u = make_uint4(f2tf32(v.x), f2tf32(v.y), f2tf32(v.z), f2tf32(v.w));
        reinterpret_cast<uint4*>(g_Wt)[i] = u;
    }
}

__device__ __forceinline__ uint32_t smem_u32(const void* p) {
    uint32_t a;
    asm("{ .reg .u64 t; cvta.to.shared.u64 t, %1; cvt.u32.u64 %0, t; }" : "=r"(a) : "l"(p));
    return a;
}

__device__ __forceinline__ void cp16(uint32_t dst, const void* src) {
    asm volatile("cp.async.cg.shared.global [%0], [%1], 16;" :: "r"(dst), "l"(src));
}

__device__ __forceinline__ void ldsm_x4(uint32_t* r, uint32_t addr) {
    asm volatile("ldmatrix.sync.aligned.m8n8.x4.shared.b16 {%0,%1,%2,%3}, [%4];"
                 : "=r"(r[0]), "=r"(r[1]), "=r"(r[2]), "=r"(r[3]) : "r"(addr));
}

__global__ __launch_bounds__(256, 2)
void dirnet_gemm_kernel(const float* __restrict__ x, const float* __restrict__ bias,
                        float* __restrict__ out) {
    extern __shared__ uint32_t sm[];
    const uint32_t smb = smem_u32(sm);

    const int o   = blockIdx.z;
    const int mt  = blockIdx.y;
    const int nt  = blockIdx.x;
    const int tid = threadIdx.x;
    const int lane = tid & 31;
    const int wid  = tid >> 5;
    const int g  = lane >> 2;   // 0..7
    const int t4 = lane & 3;    // 0..3
    const int wm = wid >> 2;    // 0..1 -> 64 rows
    const int wn = wid & 3;     // 0..3 -> 32 cols
    const int mBase = wm * 64;
    const int nBase = wn * 32;

    // ---- producer addressing: per thread 4 float4 of A (LDG->cvt->STS), 4 cp16 of B ----
    int aOff[4], bOff[4];
    uint32_t tAOff[4], tBOff[4];
    #pragma unroll
    for (int it = 0; it < 4; it++) {
        int f   = it * 256 + tid;
        int row = f >> 3;        // 0..127  (8 float4 per 32-float row)
        int c4  = f & 7;
        int m   = mt * BM + row;
        int kb  = m / J_;
        int j   = m - kb * J_;
        aOff[it]  = ((kb * O_ + o) * J_ + j) * DIM + c4 * 4;
        bOff[it]  = o * (DIM * DIM) + (nt * BN + row) * DIM + c4 * 4;
        tAOff[it] = row * ST + c4 * 4;
        tBOff[it] = (SA_U32 + row * ST + c4 * 4) * 4;  // byte offset in stage
    }

    // ---- ldmatrix per-thread source addresses (byte offsets within a stage) ----
    const int r8  = lane & 7;
    const int seg = lane >> 3;          // 0..3
    uint32_t ofA[4], ofB[2];
    #pragma unroll
    for (int mf = 0; mf < 4; mf++)
        ofA[mf] = (uint32_t)(((mBase + mf * 16 + (seg & 1) * 8 + r8) * ST + (seg >> 1) * 4) * 4);
    // B x4: matrices {nf@k0, nf@k4, nf+1@k0, nf+1@k4} for nf pair p
    #pragma unroll
    for (int p = 0; p < 2; p++)
        ofB[p] = (uint32_t)((SA_U32 + (nBase + (2 * p + (seg >> 1)) * 8 + r8) * ST
                             + (seg & 1) * 4) * 4);

    // ---- prologue: stages 0,1 in flight; A(2) prefetched to regs ----
    float4 ra[4];
    #pragma unroll
    for (int s = 0; s < 2; s++) {
        uint32_t base = smb + s * STG_U32 * 4;
        #pragma unroll
        for (int it = 0; it < 4; it++) {
            cp16(base + tBOff[it], g_Wt + bOff[it] + s * BK);
            float4 v = *reinterpret_cast<const float4*>(x + aOff[it] + s * BK);
            uint4 u = make_uint4(f2tf32(v.x), f2tf32(v.y), f2tf32(v.z), f2tf32(v.w));
            *reinterpret_cast<uint4*>(&sm[s * STG_U32 + tAOff[it]]) = u;
        }
        asm volatile("cp.async.commit_group;" ::: "memory");
    }
    #pragma unroll
    for (int it = 0; it < 4; it++)
        ra[it] = *reinterpret_cast<const float4*>(x + aOff[it] + 2 * BK);

    float acc[4][4][4];
    #pragma unroll
    for (int a = 0; a < 4; a++)
        #pragma unroll
        for (int b = 0; b < 4; b++)
            #pragma unroll
            for (int c = 0; c < 4; c++) acc[a][b][c] = 0.f;

    for (int kt = 0; kt < NKT; kt++) {
        const int cur = kt % STAGES;
        asm volatile("cp.async.wait_group 1;" ::: "memory");
        __syncthreads();

        // refill stage kt+2
        if (kt + 2 < NKT) {
            const int nxt = (kt + 2) % STAGES;
            uint32_t base = smb + nxt * STG_U32 * 4;
            #pragma unroll
            for (int it = 0; it < 4; it++) {
                cp16(base + tBOff[it], g_Wt + bOff[it] + (kt + 2) * BK);
                uint4 u = make_uint4(f2tf32(ra[it].x), f2tf32(ra[it].y),
                                     f2tf32(ra[it].z), f2tf32(ra[it].w));
                *reinterpret_cast<uint4*>(&sm[nxt * STG_U32 + tAOff[it]]) = u;
            }
        }
        asm volatile("cp.async.commit_group;" ::: "memory");
        if (kt + 3 < NKT) {
            #pragma unroll
            for (int it = 0; it < 4; it++)
                ra[it] = *reinterpret_cast<const float4*>(x + aOff[it] + (kt + 3) * BK);
        }

        const uint32_t sbase = smb + cur * STG_U32 * 4;

        #pragma unroll
        for (int ks = 0; ks < 4; ks++) {
            const uint32_t kadd = (uint32_t)(ks * 32);   // 8 u32 = 32 B per kstep
            uint32_t af[4][4], bf[2][4];
            #pragma unroll
            for (int mf = 0; mf < 4; mf++)
                ldsm_x4(af[mf], sbase + ofA[mf] + kadd);
            #pragma unroll
            for (int p = 0; p < 2; p++)
                ldsm_x4(bf[p], sbase + ofB[p] + kadd);

            #pragma unroll
            for (int mf = 0; mf < 4; mf++)
                #pragma unroll
                for (int nf = 0; nf < 4; nf++) {
                    const uint32_t* bb = &bf[nf >> 1][(nf & 1) * 2];
                    asm volatile(
                        "mma.sync.aligned.m16n8k8.row.col.f32.tf32.tf32.f32 "
                        "{%0,%1,%2,%3}, {%4,%5,%6,%7}, {%8,%9}, {%0,%1,%2,%3};\n"
                        : "+f"(acc[mf][nf][0]), "+f"(acc[mf][nf][1]),
                          "+f"(acc[mf][nf][2]), "+f"(acc[mf][nf][3])
                        : "r"(af[mf][0]), "r"(af[mf][1]), "r"(af[mf][2]), "r"(af[mf][3]),
                          "r"(bb[0]), "r"(bb[1]));
                }
        }
    }

    // ---- epilogue ----
    const float* bRow = bias + o * DIM;
    #pragma unroll
    for (int mf = 0; mf < 4; mf++) {
        #pragma unroll
        for (int half = 0; half < 2; half++) {
            int mloc = mBase + mf * 16 + g + half * 8;
            int m  = mt * BM + mloc;
            int kb = m / J_;
            int j  = m - kb * J_;
            int rowOff = ((kb * O_ + o) * J_ + j) * DIM;
            int selv = g_sel[j];
            #pragma unroll
            for (int nf = 0; nf < 4; nf++) {
                int n = nt * BN + nBase + nf * 8 + t4 * 2;
                float v0, v1;
                if (selv) {
                    v0 = acc[mf][nf][half * 2 + 0] * SCALE_F + bRow[n];
                    v1 = acc[mf][nf][half * 2 + 1] * SCALE_F + bRow[n + 1];
                } else {
                    v0 = x[rowOff + n];
                    v1 = x[rowOff + n + 1];
                }
                *reinterpret_cast<float2*>(out + rowOff + n) = make_float2(v0, v1);
            }
        }
    }
}

extern "C" void kernel_launch(void* const* d_in, const int* in_sizes, int n_in,
                              void* d_out, int out_size) {
    const float* x   = (const float*)d_in[0];
    const float* W   = (const float*)d_in[1];
    const float* b   = (const float*)d_in[2];
    const int*   idx = (const int*)d_in[3];
    float* out = (float*)d_out;

    build_sel_kernel<<<1, 32>>>(idx, in_sizes[3]);
    convert_w_kernel<<<1024, 256>>>(W);

    cudaFuncSetAttribute(dirnet_gemm_kernel,
                         cudaFuncAttributeMaxDynamicSharedMemorySize, SMEM_BYTES);

    dim3 grid(DIM / BN, M_TOTAL / BM, O_);
    dirnet_gemm_kernel<<<grid, 256, SMEM_BYTES>>>(x, b, out);
}

// round 8
// speedup vs baseline: 1.2190x; 1.0160x over previous
#include <cuda_runtime.h>
#include <cstdint>

// x (256,18,18,512) f32, W (18,512,512) f32, b (18,512) f32, idx (18) i32
#define KB_   256
#define O_    18
#define J_    18
#define DIM   512
#define M_TOTAL (KB_ * J_)        // 4608
#define BM    128
#define BN    128
#define BK    32
#define ST    36                  // smem row stride (u32): BK + 4 pad (conflict-free LDSM/STS)
#define NKT   (DIM / BK)          // 16
#define STAGES 3
#define NTHREADS 128
#define SCALE_F 0.044194173824159216f

#define SA_U32 (BM * ST)                    // 4608
#define SB_U32 (BN * ST)                    // 4608
#define STG_U32 (SA_U32 + SB_U32)           // 9216 u32 = 36864 B
#define SMEM_BYTES (STAGES * STG_U32 * 4)   // 110592

__device__ int g_sel[J_];
__device__ float g_Wt[O_ * DIM * DIM];      // W pre-converted to tf32 bit patterns

__global__ void build_sel_kernel(const int* __restrict__ idx, int n) {
    int t = threadIdx.x;
    if (t < J_) g_sel[t] = 0;
    __syncthreads();
    if (t < n) {
        int v = idx[t];
        if (v >= 0 && v < J_) g_sel[v] = 1;
    }
}

__device__ __forceinline__ uint32_t f2tf32(float f) {
    uint32_t u;
    asm("cvt.rna.tf32.f32 %0, %1;" : "=r"(u) : "f"(f));
    return u;
}

__global__ void convert_w_kernel(const float* __restrict__ W) {
    const int total4 = O_ * DIM * DIM / 4;
    for (int i = blockIdx.x * blockDim.x + threadIdx.x; i < total4;
         i += gridDim.x * blockDim.x) {
        float4 v = reinterpret_cast<const float4*>(W)[i];
        uint4 u = make_uint4(f2tf32(v.x), f2tf32(v.y), f2tf32(v.z), f2tf32(v.w));
        reinterpret_cast<uint4*>(g_Wt)[i] = u;
    }
}

__device__ __forceinline__ uint32_t smem_u32(const void* p) {
    uint32_t a;
    asm("{ .reg .u64 t; cvta.to.shared.u64 t, %1; cvt.u32.u64 %0, t; }" : "=r"(a) : "l"(p));
    return a;
}

__device__ __forceinline__ void cp16(uint32_t dst, const void* src) {
    asm volatile("cp.async.cg.shared.global [%0], [%1], 16;" :: "r"(dst), "l"(src));
}

__device__ __forceinline__ void ldsm_x4(uint32_t* r, uint32_t addr) {
    asm volatile("ldmatrix.sync.aligned.m8n8.x4.shared.b16 {%0,%1,%2,%3}, [%4];"
                 : "=r"(r[0]), "=r"(r[1]), "=r"(r[2]), "=r"(r[3]) : "r"(addr));
}

__global__ __launch_bounds__(NTHREADS, 2)
void dirnet_gemm_kernel(const float* __restrict__ x, const float* __restrict__ bias,
                        float* __restrict__ out) {
    extern __shared__ uint32_t sm[];
    const uint32_t smb = smem_u32(sm);

    const int o   = blockIdx.z;
    const int mt  = blockIdx.y;
    const int nt  = blockIdx.x;
    const int tid = threadIdx.x;
    const int lane = tid & 31;
    const int wid  = tid >> 5;          // 0..3
    const int g  = lane >> 2;           // 0..7
    const int t4 = lane & 3;            // 0..3
    const int wm = wid >> 1;            // 0..1 -> 64 rows
    const int wn = wid & 1;             // 0..1 -> 64 cols
    const int mBase = wm * 64;
    const int nBase = wn * 64;

    // ---- producer addressing: per thread 8 float4 of A (LDG->cvt->STS), 8 cp16 of B ----
    // f = tid + it*128 -> row = (tid>>3) + 16*it, c4 = tid&7 (constant per thread)
    const int rowb = tid >> 3;
    const int c4   = tid & 7;
    int aOff[8];
    #pragma unroll
    for (int it = 0; it < 8; it++) {
        int row = rowb + 16 * it;
        int m   = mt * BM + row;
        int kb  = m / J_;
        int j   = m - kb * J_;
        aOff[it] = ((kb * O_ + o) * J_ + j) * DIM + c4 * 4;
    }
    const int bOff0 = o * (DIM * DIM) + (nt * BN + rowb) * DIM + c4 * 4;   // + it*16*DIM
    const uint32_t tA0 = (uint32_t)(rowb * ST + c4 * 4);                   // + it*16*ST (u32)
    const uint32_t tB0 = (uint32_t)((SA_U32 + rowb * ST + c4 * 4) * 4);    // + it*16*ST*4 (bytes)

    // ---- ldmatrix per-thread source addresses (byte offsets within a stage) ----
    const int r8  = lane & 7;
    const int seg = lane >> 3;          // 0..3
    uint32_t ofA[4], ofB[4];
    #pragma unroll
    for (int mf = 0; mf < 4; mf++)
        ofA[mf] = (uint32_t)(((mBase + mf * 16 + (seg & 1) * 8 + r8) * ST + (seg >> 1) * 4) * 4);
    // B x4 covers nf pair {2p, 2p+1}: matrices {nf@k0, nf@k4, nf+1@k0, nf+1@k4}
    #pragma unroll
    for (int p = 0; p < 4; p++)
        ofB[p] = (uint32_t)((SA_U32 + (nBase + (2 * p + (seg >> 1)) * 8 + r8) * ST
                             + (seg & 1) * 4) * 4);

    // ---- prologue: stages 0,1 in flight; A(2) prefetched to regs ----
    float4 ra[8];
    #pragma unroll
    for (int s = 0; s < 2; s++) {
        uint32_t base = smb + s * STG_U32 * 4;
        #pragma unroll
        for (int it = 0; it < 8; it++) {
            cp16(base + tB0 + (uint32_t)(it * 16 * ST * 4),
                 g_Wt + bOff0 + it * 16 * DIM + s * BK);
            float4 v = *reinterpret_cast<const float4*>(x + aOff[it] + s * BK);
            uint4 u = make_uint4(f2tf32(v.x), f2tf32(v.y), f2tf32(v.z), f2tf32(v.w));
            *reinterpret_cast<uint4*>(&sm[s * STG_U32 + tA0 + it * 16 * ST]) = u;
        }
        asm volatile("cp.async.commit_group;" ::: "memory");
    }
    #pragma unroll
    for (int it = 0; it < 8; it++)
        ra[it] = *reinterpret_cast<const float4*>(x + aOff[it] + 2 * BK);

    float acc[4][8][4];
    #pragma unroll
    for (int a = 0; a < 4; a++)
        #pragma unroll
        for (int b = 0; b < 8; b++)
            #pragma unroll
            for (int c = 0; c < 4; c++) acc[a][b][c] = 0.f;

    for (int kt = 0; kt < NKT; kt++) {
        const int cur = kt % STAGES;
        asm volatile("cp.async.wait_group 1;" ::: "memory");
        __syncthreads();

        // refill stage kt+2
        if (kt + 2 < NKT) {
            const int nxt = (kt + 2) % STAGES;
            uint32_t base = smb + nxt * STG_U32 * 4;
            #pragma unroll
            for (int it = 0; it < 8; it++) {
                cp16(base + tB0 + (uint32_t)(it * 16 * ST * 4),
                     g_Wt + bOff0 + it * 16 * DIM + (kt + 2) * BK);
                uint4 u = make_uint4(f2tf32(ra[it].x), f2tf32(ra[it].y),
                                     f2tf32(ra[it].z), f2tf32(ra[it].w));
                *reinterpret_cast<uint4*>(&sm[nxt * STG_U32 + tA0 + it * 16 * ST]) = u;
            }
        }
        asm volatile("cp.async.commit_group;" ::: "memory");
        if (kt + 3 < NKT) {
            #pragma unroll
            for (int it = 0; it < 8; it++)
                ra[it] = *reinterpret_cast<const float4*>(x + aOff[it] + (kt + 3) * BK);
        }

        const uint32_t sbase = smb + cur * STG_U32 * 4;

        #pragma unroll
        for (int ks = 0; ks < 4; ks++) {
            const uint32_t kadd = (uint32_t)(ks * 32);   // 8 u32 = 32 B per kstep
            uint32_t af[4][4], bf[4][4];
            #pragma unroll
            for (int mf = 0; mf < 4; mf++)
                ldsm_x4(af[mf], sbase + ofA[mf] + kadd);
            #pragma unroll
            for (int p = 0; p < 4; p++)
                ldsm_x4(bf[p], sbase + ofB[p] + kadd);

            #pragma unroll
            for (int mf = 0; mf < 4; mf++)
                #pragma unroll
                for (int nf = 0; nf < 8; nf++) {
                    const uint32_t* bb = &bf[nf >> 1][(nf & 1) * 2];
                    asm volatile(
                        "mma.sync.aligned.m16n8k8.row.col.f32.tf32.tf32.f32 "
                        "{%0,%1,%2,%3}, {%4,%5,%6,%7}, {%8,%9}, {%0,%1,%2,%3};\n"
                        : "+f"(acc[mf][nf][0]), "+f"(acc[mf][nf][1]),
                          "+f"(acc[mf][nf][2]), "+f"(acc[mf][nf][3])
                        : "r"(af[mf][0]), "r"(af[mf][1]), "r"(af[mf][2]), "r"(af[mf][3]),
                          "r"(bb[0]), "r"(bb[1]));
                }
        }
    }

    // ---- epilogue ----
    const float* bRow = bias + o * DIM;
    #pragma unroll
    for (int mf = 0; mf < 4; mf++) {
        #pragma unroll
        for (int half = 0; half < 2; half++) {
            int mloc = mBase + mf * 16 + g + half * 8;
            int m  = mt * BM + mloc;
            int kb = m / J_;
            int j  = m - kb * J_;
            int rowOff = ((kb * O_ + o) * J_ + j) * DIM;
            int selv = g_sel[j];
            #pragma unroll
            for (int nf = 0; nf < 8; nf++) {
                int n = nt * BN + nBase + nf * 8 + t4 * 2;
                float v0, v1;
                if (selv) {
                    v0 = acc[mf][nf][half * 2 + 0] * SCALE_F + bRow[n];
                    v1 = acc[mf][nf][half * 2 + 1] * SCALE_F + bRow[n + 1];
                } else {
                    v0 = x[rowOff + n];
                    v1 = x[rowOff + n + 1];
                }
                *reinterpret_cast<float2*>(out + rowOff + n) = make_float2(v0, v1);
            }
        }
    }
}

extern "C" void kernel_launch(void* const* d_in, const int* in_sizes, int n_in,
                              void* d_out, int out_size) {
    const float* x   = (const float*)d_in[0];
    const float* W   = (const float*)d_in[1];
    const float* b   = (const float*)d_in[2];
    const int*   idx = (const int*)d_in[3];
    float* out = (float*)d_out;

    build_sel_kernel<<<1, 32>>>(idx, in_sizes[3]);
    convert_w_kernel<<<1024, 256>>>(W);

    cudaFuncSetAttribute(dirnet_gemm_kernel,
                         cudaFuncAttributeMaxDynamicSharedMemorySize, SMEM_BYTES);

    dim3 grid(DIM / BN, M_TOTAL / BM, O_);
    dirnet_gemm_kernel<<<grid, NTHREADS, SMEM_BYTES>>>(x, b, out);
}

// round 9
// speedup vs baseline: 1.2739x; 1.0451x over previous
#include <cuda_runtime.h>
#include <cstdint>

// x (256,18,18,512) f32, W (18,512,512) f32, b (18,512) f32, idx (18) i32
#define KB_   256
#define O_    18
#define J_    18
#define DIM   512
#define M_TOTAL (KB_ * J_)        // 4608
#define BM    128
#define BN    128
#define BK    32
#define ST    36                  // smem row stride (u32): BK + 4 pad (conflict-free LDSM/STS)
#define NKT   (DIM / BK)          // 16
#define STAGES 3
#define NTHREADS 128
#define SCALE_F 0.044194173824159216f

#define SA_U32 (BM * ST)                    // 4608
#define SB_U32 (BN * ST)                    // 4608
#define STG_U32 (SA_U32 + SB_U32)           // 9216 u32 = 36864 B
#define SMEM_BYTES (STAGES * STG_U32 * 4)   // 110592

__device__ int g_sel[J_];
__device__ float g_Wt[O_ * DIM * DIM];      // W pre-converted to tf32 bit patterns

__global__ void build_sel_kernel(const int* __restrict__ idx, int n) {
    int t = threadIdx.x;
    if (t < J_) g_sel[t] = 0;
    __syncthreads();
    if (t < n) {
        int v = idx[t];
        if (v >= 0 && v < J_) g_sel[v] = 1;
    }
}

__device__ __forceinline__ uint32_t f2tf32(float f) {
    uint32_t u;
    asm("cvt.rna.tf32.f32 %0, %1;" : "=r"(u) : "f"(f));
    return u;
}

__global__ void convert_w_kernel(const float* __restrict__ W) {
    const int total4 = O_ * DIM * DIM / 4;
    for (int i = blockIdx.x * blockDim.x + threadIdx.x; i < total4;
         i += gridDim.x * blockDim.x) {
        float4 v = reinterpret_cast<const float4*>(W)[i];
        uint4 u = make_uint4(f2tf32(v.x), f2tf32(v.y), f2tf32(v.z), f2tf32(v.w));
        reinterpret_cast<uint4*>(g_Wt)[i] = u;
    }
}

__device__ __forceinline__ uint32_t smem_u32(const void* p) {
    uint32_t a;
    asm("{ .reg .u64 t; cvta.to.shared.u64 t, %1; cvt.u32.u64 %0, t; }" : "=r"(a) : "l"(p));
    return a;
}

__device__ __forceinline__ void cp16(uint32_t dst, const void* src) {
    asm volatile("cp.async.cg.shared.global [%0], [%1], 16;" :: "r"(dst), "l"(src));
}

__device__ __forceinline__ void ldsm_x4(uint32_t* r, uint32_t addr) {
    asm volatile("ldmatrix.sync.aligned.m8n8.x4.shared.b16 {%0,%1,%2,%3}, [%4];"
                 : "=r"(r[0]), "=r"(r[1]), "=r"(r[2]), "=r"(r[3]) : "r"(addr));
}

__device__ __forceinline__ void mma_tf32(float* acc, const uint32_t* a, const uint32_t* b) {
    asm volatile(
        "mma.sync.aligned.m16n8k8.row.col.f32.tf32.tf32.f32 "
        "{%0,%1,%2,%3}, {%4,%5,%6,%7}, {%8,%9}, {%0,%1,%2,%3};\n"
        : "+f"(acc[0]), "+f"(acc[1]), "+f"(acc[2]), "+f"(acc[3])
        : "r"(a[0]), "r"(a[1]), "r"(a[2]), "r"(a[3]), "r"(b[0]), "r"(b[1]));
}

__global__ __launch_bounds__(NTHREADS, 2)
void dirnet_gemm_kernel(const float* __restrict__ x, const float* __restrict__ bias,
                        float* __restrict__ out) {
    extern __shared__ uint32_t sm[];
    const uint32_t smb = smem_u32(sm);

    const int o   = blockIdx.z;
    const int mt  = blockIdx.y;
    const int nt  = blockIdx.x;
    const int tid = threadIdx.x;
    const int lane = tid & 31;
    const int wid  = tid >> 5;          // 0..3
    const int g  = lane >> 2;           // 0..7
    const int t4 = lane & 3;            // 0..3
    const int wm = wid >> 1;            // 0..1 -> 64 rows
    const int wn = wid & 1;             // 0..1 -> 64 cols
    const int mBase = wm * 64;
    const int nBase = wn * 64;

    // ---- producer addressing: per thread 8 float4 of A (LDG->cvt->STS), 8 cp16 of B ----
    const int rowb = tid >> 3;
    const int c4   = tid & 7;
    int aOff[8];
    #pragma unroll
    for (int it = 0; it < 8; it++) {
        int row = rowb + 16 * it;
        int m   = mt * BM + row;
        int kb  = m / J_;
        int j   = m - kb * J_;
        aOff[it] = ((kb * O_ + o) * J_ + j) * DIM + c4 * 4;
    }
    const int bOff0 = o * (DIM * DIM) + (nt * BN + rowb) * DIM + c4 * 4;   // + it*16*DIM
    const uint32_t tA0 = (uint32_t)(rowb * ST + c4 * 4);                   // + it*16*ST (u32)
    const uint32_t tB0 = (uint32_t)((SA_U32 + rowb * ST + c4 * 4) * 4);    // + it*16*ST*4 (bytes)

    // ---- ldmatrix per-thread source addresses (byte offsets within a stage) ----
    const int r8  = lane & 7;
    const int seg = lane >> 3;          // 0..3
    uint32_t ofA[4], ofB[4];
    #pragma unroll
    for (int mf = 0; mf < 4; mf++)
        ofA[mf] = (uint32_t)(((mBase + mf * 16 + (seg & 1) * 8 + r8) * ST + (seg >> 1) * 4) * 4);
    #pragma unroll
    for (int p = 0; p < 4; p++)
        ofB[p] = (uint32_t)((SA_U32 + (nBase + (2 * p + (seg >> 1)) * 8 + r8) * ST
                             + (seg & 1) * 4) * 4);

    // ---- prologue: stages 0,1 in flight; A(2) prefetched to regs ----
    float4 ra[8];
    #pragma unroll
    for (int s = 0; s < 2; s++) {
        uint32_t base = smb + s * STG_U32 * 4;
        #pragma unroll
        for (int it = 0; it < 8; it++) {
            cp16(base + tB0 + (uint32_t)(it * 16 * ST * 4),
                 g_Wt + bOff0 + it * 16 * DIM + s * BK);
            float4 v = *reinterpret_cast<const float4*>(x + aOff[it] + s * BK);
            uint4 u = make_uint4(f2tf32(v.x), f2tf32(v.y), f2tf32(v.z), f2tf32(v.w));
            *reinterpret_cast<uint4*>(&sm[s * STG_U32 + tA0 + it * 16 * ST]) = u;
        }
        asm volatile("cp.async.commit_group;" ::: "memory");
    }
    #pragma unroll
    for (int it = 0; it < 8; it++)
        ra[it] = *reinterpret_cast<const float4*>(x + aOff[it] + 2 * BK);

    float acc[4][8][4];
    #pragma unroll
    for (int a = 0; a < 4; a++)
        #pragma unroll
        for (int b = 0; b < 8; b++)
            #pragma unroll
            for (int c = 0; c < 4; c++) acc[a][b][c] = 0.f;

    for (int kt = 0; kt < NKT; kt++) {
        const int cur = kt % STAGES;
        asm volatile("cp.async.wait_group 1;" ::: "memory");
        __syncthreads();

        const uint32_t sbase = smb + cur * STG_U32 * 4;

        // ---- kstep 0 first: tensor pipe starts immediately after the barrier ----
        {
            uint32_t af[4][4], bf[4][4];
            #pragma unroll
            for (int mf = 0; mf < 4; mf++) ldsm_x4(af[mf], sbase + ofA[mf]);
            #pragma unroll
            for (int p = 0; p < 4; p++)   ldsm_x4(bf[p], sbase + ofB[p]);
            #pragma unroll
            for (int mf = 0; mf < 4; mf++)
                #pragma unroll
                for (int nf = 0; nf < 8; nf++)
                    mma_tf32(acc[mf][nf], af[mf], &bf[nf >> 1][(nf & 1) * 2]);
        }

        // ---- producer for stage kt+2, overlapped with ksteps 1-3 below ----
        if (kt + 2 < NKT) {
            const int nxt = (kt + 2) % STAGES;
            uint32_t base = smb + nxt * STG_U32 * 4;
            #pragma unroll
            for (int it = 0; it < 8; it++) {
                cp16(base + tB0 + (uint32_t)(it * 16 * ST * 4),
                     g_Wt + bOff0 + it * 16 * DIM + (kt + 2) * BK);
                uint4 u = make_uint4(f2tf32(ra[it].x), f2tf32(ra[it].y),
                                     f2tf32(ra[it].z), f2tf32(ra[it].w));
                *reinterpret_cast<uint4*>(&sm[nxt * STG_U32 + tA0 + it * 16 * ST]) = u;
            }
        }
        asm volatile("cp.async.commit_group;" ::: "memory");
        if (kt + 3 < NKT) {
            #pragma unroll
            for (int it = 0; it < 8; it++)
                ra[it] = *reinterpret_cast<const float4*>(x + aOff[it] + (kt + 3) * BK);
        }

        // ---- ksteps 1-3 ----
        #pragma unroll
        for (int ks = 1; ks < 4; ks++) {
            const uint32_t kadd = (uint32_t)(ks * 32);
            uint32_t af[4][4], bf[4][4];
            #pragma unroll
            for (int mf = 0; mf < 4; mf++) ldsm_x4(af[mf], sbase + ofA[mf] + kadd);
            #pragma unroll
            for (int p = 0; p < 4; p++)   ldsm_x4(bf[p], sbase + ofB[p] + kadd);
            #pragma unroll
            for (int mf = 0; mf < 4; mf++)
                #pragma unroll
                for (int nf = 0; nf < 8; nf++)
                    mma_tf32(acc[mf][nf], af[mf], &bf[nf >> 1][(nf & 1) * 2]);
        }
    }

    // ---- epilogue ----
    const float* bRow = bias + o * DIM;
    #pragma unroll
    for (int mf = 0; mf < 4; mf++) {
        #pragma unroll
        for (int half = 0; half < 2; half++) {
            int mloc = mBase + mf * 16 + g + half * 8;
            int m  = mt * BM + mloc;
            int kb = m / J_;
            int j  = m - kb * J_;
            int rowOff = ((kb * O_ + o) * J_ + j) * DIM;
            int selv = g_sel[j];
            #pragma unroll
            for (int nf = 0; nf < 8; nf++) {
                int n = nt * BN + nBase + nf * 8 + t4 * 2;
                float v0, v1;
                if (selv) {
                    v0 = acc[mf][nf][half * 2 + 0] * SCALE_F + bRow[n];
                    v1 = acc[mf][nf][half * 2 + 1] * SCALE_F + bRow[n + 1];
                } else {
                    v0 = x[rowOff + n];
                    v1 = x[rowOff + n + 1];
                }
                *reinterpret_cast<float2*>(out + rowOff + n) = make_float2(v0, v1);
            }
        }
    }
}

extern "C" void kernel_launch(void* const* d_in, const int* in_sizes, int n_in,
                              void* d_out, int out_size) {
    const float* x   = (const float*)d_in[0];
    const float* W   = (const float*)d_in[1];
    const float* b   = (const float*)d_in[2];
    const int*   idx = (const int*)d_in[3];
    float* out = (float*)d_out;

    build_sel_kernel<<<1, 32>>>(idx, in_sizes[3]);
    convert_w_kernel<<<1024, 256>>>(W);

    cudaFuncSetAttribute(dirnet_gemm_kernel,
                         cudaFuncAttributeMaxDynamicSharedMemorySize, SMEM_BYTES);

    dim3 grid(DIM / BN, M_TOTAL / BM, O_);
    dirnet_gemm_kernel<<<grid, NTHREADS, SMEM_BYTES>>>(x, b, out);
}

// round 10
// speedup vs baseline: 1.2817x; 1.0061x over previous
#include <cuda_runtime.h>
#include <cstdint>

// x (256,18,18,512) f32, W (18,512,512) f32, b (18,512) f32, idx (18) i32
#define KB_   256
#define O_    18
#define J_    18
#define DIM   512
#define M_TOTAL (KB_ * J_)        // 4608
#define BM    128
#define BN    128
#define BK    32
#define ST    36                  // smem row stride (u32): BK + 4 pad (conflict-free LDSM/STS)
#define NKT   (DIM / BK)          // 16
#define STAGES 3
#define NTHREADS 128
#define SCALE_F 0.044194173824159216f

#define SA_U32 (BM * ST)                    // 4608
#define SB_U32 (BN * ST)                    // 4608
#define STG_U32 (SA_U32 + SB_U32)           // 9216 u32 = 36864 B
#define SMEM_BYTES (STAGES * STG_U32 * 4)   // 110592

__device__ int g_sel[J_];
__device__ float g_Wt[O_ * DIM * DIM];      // W pre-converted to tf32 bit patterns

__global__ void build_sel_kernel(const int* __restrict__ idx, int n) {
    int t = threadIdx.x;
    if (t < J_) g_sel[t] = 0;
    __syncthreads();
    if (t < n) {
        int v = idx[t];
        if (v >= 0 && v < J_) g_sel[v] = 1;
    }
}

__device__ __forceinline__ uint32_t f2tf32(float f) {
    uint32_t u;
    asm("cvt.rna.tf32.f32 %0, %1;" : "=r"(u) : "f"(f));
    return u;
}

__global__ void convert_w_kernel(const float* __restrict__ W) {
    const int total4 = O_ * DIM * DIM / 4;
    for (int i = blockIdx.x * blockDim.x + threadIdx.x; i < total4;
         i += gridDim.x * blockDim.x) {
        float4 v = reinterpret_cast<const float4*>(W)[i];
        uint4 u = make_uint4(f2tf32(v.x), f2tf32(v.y), f2tf32(v.z), f2tf32(v.w));
        reinterpret_cast<uint4*>(g_Wt)[i] = u;
    }
}

__device__ __forceinline__ uint32_t smem_u32(const void* p) {
    uint32_t a;
    asm("{ .reg .u64 t; cvta.to.shared.u64 t, %1; cvt.u32.u64 %0, t; }" : "=r"(a) : "l"(p));
    return a;
}

__device__ __forceinline__ void cp16(uint32_t dst, const void* src) {
    asm volatile("cp.async.cg.shared.global [%0], [%1], 16;" :: "r"(dst), "l"(src));
}

__device__ __forceinline__ void ldsm_x4(uint32_t* r, uint32_t addr) {
    asm volatile("ldmatrix.sync.aligned.m8n8.x4.shared.b16 {%0,%1,%2,%3}, [%4];"
                 : "=r"(r[0]), "=r"(r[1]), "=r"(r[2]), "=r"(r[3]) : "r"(addr));
}

__device__ __forceinline__ void mma_tf32(float* acc, const uint32_t* a, const uint32_t* b) {
    asm volatile(
        "mma.sync.aligned.m16n8k8.row.col.f32.tf32.tf32.f32 "
        "{%0,%1,%2,%3}, {%4,%5,%6,%7}, {%8,%9}, {%0,%1,%2,%3};\n"
        : "+f"(acc[0]), "+f"(acc[1]), "+f"(acc[2]), "+f"(acc[3])
        : "r"(a[0]), "r"(a[1]), "r"(a[2]), "r"(a[3]), "r"(b[0]), "r"(b[1]));
}

__global__ __launch_bounds__(NTHREADS, 2)
void dirnet_gemm_kernel(const float* __restrict__ x, const float* __restrict__ bias,
                        float* __restrict__ out) {
    extern __shared__ uint32_t sm[];
    const uint32_t smb = smem_u32(sm);

    const int o   = blockIdx.z;
    const int mt  = blockIdx.y;
    const int nt  = blockIdx.x;
    const int tid = threadIdx.x;
    const int lane = tid & 31;
    const int wid  = tid >> 5;          // 0..3
    const int g  = lane >> 2;           // 0..7
    const int t4 = lane & 3;            // 0..3
    const int wm = wid >> 1;            // 0..1 -> 64 rows
    const int wn = wid & 1;             // 0..1 -> 64 cols
    const int mBase = wm * 64;
    const int nBase = wn * 64;

    // ---- producer addressing: per thread 8 float4 of A (LDG->cvt->STS), 8 cp16 of B ----
    const int rowb = tid >> 3;
    const int c4   = tid & 7;
    int aOff[8];
    #pragma unroll
    for (int it = 0; it < 8; it++) {
        int row = rowb + 16 * it;
        int m   = mt * BM + row;
        int kb  = m / J_;
        int j   = m - kb * J_;
        aOff[it] = ((kb * O_ + o) * J_ + j) * DIM + c4 * 4;
    }
    const int bOff0 = o * (DIM * DIM) + (nt * BN + rowb) * DIM + c4 * 4;   // + it*16*DIM
    const uint32_t tA0 = (uint32_t)(rowb * ST + c4 * 4);                   // + it*16*ST (u32)
    const uint32_t tB0 = (uint32_t)((SA_U32 + rowb * ST + c4 * 4) * 4);    // + it*16*ST*4 (bytes)

    // ---- ldmatrix per-thread source addresses (byte offsets within a stage) ----
    const int r8  = lane & 7;
    const int seg = lane >> 3;          // 0..3
    uint32_t ofA[4], ofB[4];
    #pragma unroll
    for (int mf = 0; mf < 4; mf++)
        ofA[mf] = (uint32_t)(((mBase + mf * 16 + (seg & 1) * 8 + r8) * ST + (seg >> 1) * 4) * 4);
    #pragma unroll
    for (int p = 0; p < 4; p++)
        ofB[p] = (uint32_t)((SA_U32 + (nBase + (2 * p + (seg >> 1)) * 8 + r8) * ST
                             + (seg & 1) * 4) * 4);

    // ---- prologue: stages 0,1 in flight; A(2) prefetched to regs ----
    float4 ra[8];
    #pragma unroll
    for (int s = 0; s < 2; s++) {
        uint32_t base = smb + s * STG_U32 * 4;
        #pragma unroll
        for (int it = 0; it < 8; it++) {
            cp16(base + tB0 + (uint32_t)(it * 16 * ST * 4),
                 g_Wt + bOff0 + it * 16 * DIM + s * BK);
            float4 v = *reinterpret_cast<const float4*>(x + aOff[it] + s * BK);
            uint4 u = make_uint4(f2tf32(v.x), f2tf32(v.y), f2tf32(v.z), f2tf32(v.w));
            *reinterpret_cast<uint4*>(&sm[s * STG_U32 + tA0 + it * 16 * ST]) = u;
        }
        asm volatile("cp.async.commit_group;" ::: "memory");
    }
    #pragma unroll
    for (int it = 0; it < 8; it++)
        ra[it] = *reinterpret_cast<const float4*>(x + aOff[it] + 2 * BK);

    float acc[4][8][4];
    #pragma unroll
    for (int a = 0; a < 4; a++)
        #pragma unroll
        for (int b = 0; b < 8; b++)
            #pragma unroll
            for (int c = 0; c < 4; c++) acc[a][b][c] = 0.f;

    // double-buffered fragments
    uint32_t afd[2][4][4], bfd[2][4][4];

    for (int kt = 0; kt < NKT; kt++) {
        const int cur = kt % STAGES;
        asm volatile("cp.async.wait_group 1;" ::: "memory");
        __syncthreads();

        const uint32_t sbase = smb + cur * STG_U32 * 4;

        // fragments for ks=0 and ks=1
        #pragma unroll
        for (int mf = 0; mf < 4; mf++) ldsm_x4(afd[0][mf], sbase + ofA[mf]);
        #pragma unroll
        for (int p = 0; p < 4; p++)   ldsm_x4(bfd[0][p], sbase + ofB[p]);
        #pragma unroll
        for (int mf = 0; mf < 4; mf++) ldsm_x4(afd[1][mf], sbase + ofA[mf] + 32);
        #pragma unroll
        for (int p = 0; p < 4; p++)   ldsm_x4(bfd[1][p], sbase + ofB[p] + 32);

        // MMA ks=0 (overlaps with ks=1 ldsm in flight)
        #pragma unroll
        for (int mf = 0; mf < 4; mf++)
            #pragma unroll
            for (int nf = 0; nf < 8; nf++)
                mma_tf32(acc[mf][nf], afd[0][mf], &bfd[0][nf >> 1][(nf & 1) * 2]);

        // producer for stage kt+2 (overlapped with remaining MMAs)
        if (kt + 2 < NKT) {
            const int nxt = (kt + 2) % STAGES;
            uint32_t base = smb + nxt * STG_U32 * 4;
            #pragma unroll
            for (int it = 0; it < 8; it++) {
                cp16(base + tB0 + (uint32_t)(it * 16 * ST * 4),
                     g_Wt + bOff0 + it * 16 * DIM + (kt + 2) * BK);
                uint4 u = make_uint4(f2tf32(ra[it].x), f2tf32(ra[it].y),
                                     f2tf32(ra[it].z), f2tf32(ra[it].w));
                *reinterpret_cast<uint4*>(&sm[nxt * STG_U32 + tA0 + it * 16 * ST]) = u;
            }
        }
        asm volatile("cp.async.commit_group;" ::: "memory");

        // fragments ks=2 into buf0; MMA ks=1
        #pragma unroll
        for (int mf = 0; mf < 4; mf++) ldsm_x4(afd[0][mf], sbase + ofA[mf] + 64);
        #pragma unroll
        for (int p = 0; p < 4; p++)   ldsm_x4(bfd[0][p], sbase + ofB[p] + 64);
        #pragma unroll
        for (int mf = 0; mf < 4; mf++)
            #pragma unroll
            for (int nf = 0; nf < 8; nf++)
                mma_tf32(acc[mf][nf], afd[1][mf], &bfd[1][nf >> 1][(nf & 1) * 2]);

        // A prefetch for kt+3
        if (kt + 3 < NKT) {
            #pragma unroll
            for (int it = 0; it < 8; it++)
                ra[it] = *reinterpret_cast<const float4*>(x + aOff[it] + (kt + 3) * BK);
        }

        // fragments ks=3 into buf1; MMA ks=2
        #pragma unroll
        for (int mf = 0; mf < 4; mf++) ldsm_x4(afd[1][mf], sbase + ofA[mf] + 96);
        #pragma unroll
        for (int p = 0; p < 4; p++)   ldsm_x4(bfd[1][p], sbase + ofB[p] + 96);
        #pragma unroll
        for (int mf = 0; mf < 4; mf++)
            #pragma unroll
            for (int nf = 0; nf < 8; nf++)
                mma_tf32(acc[mf][nf], afd[0][mf], &bfd[0][nf >> 1][(nf & 1) * 2]);

        // MMA ks=3
        #pragma unroll
        for (int mf = 0; mf < 4; mf++)
            #pragma unroll
            for (int nf = 0; nf < 8; nf++)
                mma_tf32(acc[mf][nf], afd[1][mf], &bfd[1][nf >> 1][(nf & 1) * 2]);
    }

    // ---- epilogue ----
    const float* bRow = bias + o * DIM;
    #pragma unroll
    for (int mf = 0; mf < 4; mf++) {
        #pragma unroll
        for (int half = 0; half < 2; half++) {
            int mloc = mBase + mf * 16 + g + half * 8;
            int m  = mt * BM + mloc;
            int kb = m / J_;
            int j  = m - kb * J_;
            int rowOff = ((kb * O_ + o) * J_ + j) * DIM;
            int selv = g_sel[j];
            #pragma unroll
            for (int nf = 0; nf < 8; nf++) {
                int n = nt * BN + nBase + nf * 8 + t4 * 2;
                float v0, v1;
                if (selv) {
                    v0 = acc[mf][nf][half * 2 + 0] * SCALE_F + bRow[n];
                    v1 = acc[mf][nf][half * 2 + 1] * SCALE_F + bRow[n + 1];
                } else {
                    v0 = x[rowOff + n];
                    v1 = x[rowOff + n + 1];
                }
                *reinterpret_cast<float2*>(out + rowOff + n) = make_float2(v0, v1);
            }
        }
    }
}

extern "C" void kernel_launch(void* const* d_in, const int* in_sizes, int n_in,
                              void* d_out, int out_size) {
    const float* x   = (const float*)d_in[0];
    const float* W   = (const float*)d_in[1];
    const float* b   = (const float*)d_in[2];
    const int*   idx = (const int*)d_in[3];
    float* out = (float*)d_out;

    build_sel_kernel<<<1, 32>>>(idx, in_sizes[3]);
    convert_w_kernel<<<1024, 256>>>(W);

    cudaFuncSetAttribute(dirnet_gemm_kernel,
                         cudaFuncAttributeMaxDynamicSharedMemorySize, SMEM_BYTES);

    dim3 grid(DIM / BN, M_TOTAL / BM, O_);
    dirnet_gemm_kernel<<<grid, NTHREADS, SMEM_BYTES>>>(x, b, out);
}